// round 2
// baseline (speedup 1.0000x reference)
#include <cuda_runtime.h>
#include <cuda_bf16.h>
#include <math.h>

// Problem constants
#define BB 2
#define TT 2048
#define DM 2048
#define HH 16
#define DK 128
#define DV 128
#define KW 4
#define CDIM 6144          // 2*H*DK + H*DV
#define MTOK 4096          // B*T

// ---------------- scratch (device globals; no allocation allowed) ----------------
__device__ float g_mixed[(size_t)MTOK * CDIM];
__device__ float g_y[(size_t)MTOK * CDIM];
__device__ float g_qn[(size_t)MTOK * 2048];
__device__ float g_kn[(size_t)MTOK * 2048];
__device__ float g_beta[(size_t)MTOK * HH];
__device__ float g_decay[(size_t)MTOK * HH];
__device__ float g_o[(size_t)MTOK * 2048];
__device__ float g_z[(size_t)MTOK * 2048];
__device__ float g_on[(size_t)MTOK * 2048];

// ---------------- generic SGEMM: C[m,n] = sum_k A[m*K+k]*W[n*K+k] ----------------
// 128x128 tile, TK=8, 256 threads, 8x8 per thread, double-buffered smem.
__global__ __launch_bounds__(256, 2) void gemm_nt(const float* __restrict__ A,
                                                  const float* __restrict__ W,
                                                  float* __restrict__ C,
                                                  int M, int N, int K) {
    __shared__ __align__(16) float As[2][8][128];
    __shared__ __align__(16) float Ws[2][8][128];
    const int tid = threadIdx.x;
    const int bm = blockIdx.y * 128, bn = blockIdx.x * 128;
    const int lr = tid >> 1;
    const int lk = (tid & 1) << 2;
    const float* Ap = A + (size_t)(bm + lr) * K + lk;
    const float* Wp = W + (size_t)(bn + lr) * K + lk;
    const int tx = tid & 15, ty = tid >> 4;

    float acc[8][8];
#pragma unroll
    for (int i = 0; i < 8; i++)
#pragma unroll
        for (int j = 0; j < 8; j++) acc[i][j] = 0.f;

    float4 a = *(const float4*)Ap;
    float4 w = *(const float4*)Wp;
    As[0][lk + 0][lr] = a.x; As[0][lk + 1][lr] = a.y;
    As[0][lk + 2][lr] = a.z; As[0][lk + 3][lr] = a.w;
    Ws[0][lk + 0][lr] = w.x; Ws[0][lk + 1][lr] = w.y;
    Ws[0][lk + 2][lr] = w.z; Ws[0][lk + 3][lr] = w.w;
    __syncthreads();

    int buf = 0;
    for (int k0 = 8; k0 <= K; k0 += 8) {
        const bool more = (k0 < K);
        if (more) {
            a = *(const float4*)(Ap + k0);
            w = *(const float4*)(Wp + k0);
        }
#pragma unroll
        for (int kk = 0; kk < 8; kk++) {
            float4 a0 = *(const float4*)&As[buf][kk][ty * 4];
            float4 a1 = *(const float4*)&As[buf][kk][64 + ty * 4];
            float4 b0 = *(const float4*)&Ws[buf][kk][tx * 4];
            float4 b1 = *(const float4*)&Ws[buf][kk][64 + tx * 4];
            float av[8] = {a0.x, a0.y, a0.z, a0.w, a1.x, a1.y, a1.z, a1.w};
            float bv[8] = {b0.x, b0.y, b0.z, b0.w, b1.x, b1.y, b1.z, b1.w};
#pragma unroll
            for (int i = 0; i < 8; i++)
#pragma unroll
                for (int j = 0; j < 8; j++) acc[i][j] += av[i] * bv[j];
        }
        if (more) {
            buf ^= 1;
            As[buf][lk + 0][lr] = a.x; As[buf][lk + 1][lr] = a.y;
            As[buf][lk + 2][lr] = a.z; As[buf][lk + 3][lr] = a.w;
            Ws[buf][lk + 0][lr] = w.x; Ws[buf][lk + 1][lr] = w.y;
            Ws[buf][lk + 2][lr] = w.z; Ws[buf][lk + 3][lr] = w.w;
            __syncthreads();
        }
    }

#pragma unroll
    for (int i = 0; i < 8; i++) {
        int row = bm + ((i < 4) ? (ty * 4 + i) : (64 + ty * 4 + (i - 4)));
        float4 v0 = make_float4(acc[i][0], acc[i][1], acc[i][2], acc[i][3]);
        float4 v1 = make_float4(acc[i][4], acc[i][5], acc[i][6], acc[i][7]);
        *(float4*)(C + (size_t)row * N + bn + tx * 4) = v0;
        *(float4*)(C + (size_t)row * N + bn + 64 + tx * 4) = v1;
    }
}

// ---------------- gates: beta = sigmoid(x.w_b), decay = exp(-exp(A_log)*softplus(x.w_a+dt_bias)) ----
__global__ __launch_bounds__(256) void proj_gates(const float* __restrict__ x,
                                                  const float* __restrict__ w_b,
                                                  const float* __restrict__ w_a,
                                                  const float* __restrict__ dt_bias,
                                                  const float* __restrict__ A_log) {
    const int m = blockIdx.x;
    __shared__ float xs[DM];
    for (int i = threadIdx.x; i < DM; i += 256) xs[i] = x[(size_t)m * DM + i];
    __syncthreads();
    const int warp = threadIdx.x >> 5, lane = threadIdx.x & 31;
    for (int d = warp; d < 32; d += 8) {
        const float* w = (d < HH) ? (w_b + (size_t)d * DM) : (w_a + (size_t)(d - HH) * DM);
        float s = 0.f;
        for (int i = lane; i < DM; i += 32) s += xs[i] * w[i];
#pragma unroll
        for (int off = 16; off; off >>= 1) s += __shfl_xor_sync(0xffffffffu, s, off);
        if (lane == 0) {
            if (d < HH) {
                g_beta[(size_t)m * HH + d] = 1.f / (1.f + expf(-s));
            } else {
                int h = d - HH;
                float sp = s + dt_bias[h];
                sp = (sp > 20.f) ? sp : log1pf(expf(sp));
                g_decay[(size_t)m * HH + h] = expf(-expf(A_log[h]) * sp);
            }
        }
    }
}

// ---------------- causal depthwise conv (KW=4) + SiLU ----------------
__global__ __launch_bounds__(256) void conv_silu(const float* __restrict__ conv_w) {
    const int c = blockIdx.x * 256 + threadIdx.x;
    const int bt = blockIdx.y;
    const int t = bt & (TT - 1);
    const float* base = g_mixed + (size_t)bt * CDIM + c;
    float4 w = *(const float4*)(conv_w + (size_t)c * KW);
    float acc = w.w * base[0];
    if (t >= 1) acc += w.z * base[-(ptrdiff_t)CDIM];
    if (t >= 2) acc += w.y * base[-(ptrdiff_t)(2 * CDIM)];
    if (t >= 3) acc += w.x * base[-(ptrdiff_t)(3 * CDIM)];
    float s = acc / (1.f + expf(-acc));
    g_y[(size_t)bt * CDIM + c] = s;
}

// ---------------- per-head L2 norm of q and k ----------------
__global__ __launch_bounds__(128) void qk_norm() {
    const int bt = blockIdx.x;
    const int hh = blockIdx.y;  // 0..15 q, 16..31 k
    const int off = (hh < HH) ? hh * DK : (HH * DK + (hh - HH) * DK);
    const float* src = g_y + (size_t)bt * CDIM + off;
    float u = src[threadIdx.x];
    float s = u * u;
#pragma unroll
    for (int o = 16; o; o >>= 1) s += __shfl_xor_sync(0xffffffffu, s, o);
    __shared__ float red[4];
    if ((threadIdx.x & 31) == 0) red[threadIdx.x >> 5] = s;
    __syncthreads();
    float tot = red[0] + red[1] + red[2] + red[3];
    float r = rsqrtf(tot + 1e-6f);
    float* dst = (hh < HH) ? g_qn : g_kn;
    dst[(size_t)bt * 2048 + (hh & 15) * DK + threadIdx.x] = u * r;
}

// ---------------- sequential delta-rule scan ----------------
// grid: (B*H, 4 j-chunks), block 128 = (32 j-cols x 4 k-groups).
// thread (kg, jloc) holds S[kg*32 .. kg*32+31][jcol] in registers.
__global__ __launch_bounds__(128) void scan_kernel(float* __restrict__ o) {
    const int bh = blockIdx.x;
    const int b = bh >> 4, h = bh & 15;
    const int jc = blockIdx.y;
    const int tid = threadIdx.x;
    const int jloc = tid >> 2;
    const int kg = tid & 3;

    __shared__ float ks[2][132], qs[2][132], vs[2][32], sc[2][2];
    float S[32];
#pragma unroll
    for (int i = 0; i < 32; i++) S[i] = 0.f;

    const int skew = (tid >> 5) * 33 + (tid & 31);  // conflict-free layout slot for k idx = tid

    const size_t qkbase = ((size_t)b * TT) * 2048 + h * DK;
    const size_t vbase = ((size_t)b * TT) * CDIM + 2 * HH * DK + h * DV + jc * 32;
    const size_t gbase = ((size_t)b * TT) * HH + h;
    const size_t obase = ((size_t)b * TT) * 2048 + h * DV + jc * 32 + jloc;

    // preload t=0
    float rk = g_kn[qkbase + tid];
    float rq = g_qn[qkbase + tid];
    float rv = (tid < 32) ? g_y[vbase + tid] : 0.f;
    float rb = g_beta[gbase], rd = g_decay[gbase];
    ks[0][skew] = rk;
    qs[0][skew] = rq;
    if (tid < 32) vs[0][tid] = rv;
    if (tid == 0) { sc[0][0] = rb; sc[0][1] = rd; }
    __syncthreads();

    for (int t = 0; t < TT; t++) {
        const int cur = t & 1;
        if (t + 1 < TT) {
            const size_t to = (size_t)(t + 1);
            rk = g_kn[qkbase + to * 2048 + tid];
            rq = g_qn[qkbase + to * 2048 + tid];
            if (tid < 32) rv = g_y[vbase + to * CDIM + tid];
            rb = g_beta[gbase + to * HH];
            rd = g_decay[gbase + to * HH];
        }
        const float bet = sc[cur][0];
        const float dec = sc[cur][1];
        const float vv = vs[cur][jloc];

        float kreg[32];
        float kv = 0.f;
#pragma unroll
        for (int i = 0; i < 32; i++) {
            kreg[i] = ks[cur][kg * 33 + i];
            S[i] *= dec;
            kv += kreg[i] * S[i];
        }
        kv += __shfl_xor_sync(0xffffffffu, kv, 1);
        kv += __shfl_xor_sync(0xffffffffu, kv, 2);
        const float delta = (vv - kv) * bet;

        float oacc = 0.f;
#pragma unroll
        for (int i = 0; i < 32; i++) {
            S[i] += kreg[i] * delta;
            oacc += qs[cur][kg * 33 + i] * S[i];
        }
        oacc += __shfl_xor_sync(0xffffffffu, oacc, 1);
        oacc += __shfl_xor_sync(0xffffffffu, oacc, 2);
        if (kg == 0) o[obase + (size_t)t * 2048] = oacc;

        if (t + 1 < TT) {
            const int nxt = cur ^ 1;
            ks[nxt][skew] = rk;
            qs[nxt][skew] = rq;
            if (tid < 32) vs[nxt][tid] = rv;
            if (tid == 0) { sc[nxt][0] = rb; sc[nxt][1] = rd; }
        }
        __syncthreads();
    }
}

// ---------------- gated RMSNorm per head ----------------
__global__ __launch_bounds__(128) void gated_norm(const float* __restrict__ norm_w) {
    const int g = blockIdx.x;  // bt*16 + h
    float u = g_o[(size_t)g * DV + threadIdx.x];
    float s = u * u;
#pragma unroll
    for (int o = 16; o; o >>= 1) s += __shfl_xor_sync(0xffffffffu, s, o);
    __shared__ float red[4];
    if ((threadIdx.x & 31) == 0) red[threadIdx.x >> 5] = s;
    __syncthreads();
    float tot = red[0] + red[1] + red[2] + red[3];
    float r = rsqrtf(tot * (1.f / DV) + 1e-6f);
    float zz = g_z[(size_t)g * DV + threadIdx.x];
    float sil = zz / (1.f + expf(-zz));
    g_on[(size_t)g * DV + threadIdx.x] = u * r * norm_w[threadIdx.x] * sil;
}

// ---------------- launch ----------------
extern "C" void kernel_launch(void* const* d_in, const int* in_sizes, int n_in,
                              void* d_out, int out_size) {
    const float* x = (const float*)d_in[0];
    const float* w_qkv = (const float*)d_in[1];
    const float* conv_w = (const float*)d_in[2];
    const float* w_z = (const float*)d_in[3];
    const float* w_b = (const float*)d_in[4];
    const float* w_a = (const float*)d_in[5];
    const float* dt_bias = (const float*)d_in[6];
    const float* A_log = (const float*)d_in[7];
    const float* norm_w = (const float*)d_in[8];
    const float* w_out = (const float*)d_in[9];
    float* out = (float*)d_out;

    float* mixed; cudaGetSymbolAddress((void**)&mixed, g_mixed);
    float* z;     cudaGetSymbolAddress((void**)&z, g_z);
    float* o;     cudaGetSymbolAddress((void**)&o, g_o);
    float* on;    cudaGetSymbolAddress((void**)&on, g_on);

    // 1. mixed = x @ w_qkv^T   [4096 x 6144]
    gemm_nt<<<dim3(CDIM / 128, MTOK / 128), 256>>>(x, w_qkv, mixed, MTOK, CDIM, DM);
    // 2. gates
    proj_gates<<<MTOK, 256>>>(x, w_b, w_a, dt_bias, A_log);
    // 3. conv + silu
    conv_silu<<<dim3(CDIM / 256, MTOK), 256>>>(conv_w);
    // 4. q/k l2 norm
    qk_norm<<<dim3(MTOK, 2 * HH), 128>>>();
    // 5. z = x @ w_z^T  [4096 x 2048]
    gemm_nt<<<dim3(2048 / 128, MTOK / 128), 256>>>(x, w_z, z, MTOK, 2048, DM);
    // 6. scan
    scan_kernel<<<dim3(BB * HH, 4), 128>>>(o);
    // 7. gated rmsnorm
    gated_norm<<<MTOK * HH, 128>>>(norm_w);
    // 8. out = on @ w_out^T  [4096 x 2048]
    gemm_nt<<<dim3(2048 / 128, MTOK / 128), 256>>>(on, w_out, out, MTOK, 2048, DM);
}